// round 8
// baseline (speedup 1.0000x reference)
#include <cuda_runtime.h>
#include <math.h>
#include <stdint.h>

// ---------------------------------------------------------------------------
// FedTGPClientLoss:
//   ce    = mean_b [ logsumexp(logits[b,:]) - logits[b, label_b] ]   (0 if !finite)
//   proto = mean_b mean_d (features[b,d] - protos[label_b, d])^2
//   total = ce + proto                                               (ce if !finite)
// Output: [total, ce, proto]  (3 x f32)
//
// One WARP per row. Single-pass sum-of-exp (no max subtraction -- exact and
// overflow-free for |logit| < 88) with a warp-uniform two-pass max-subtracted
// fallback for extreme inputs. Fused grid reduction via threadfence pattern.
// ---------------------------------------------------------------------------

#define MAXBLK 8192
__device__ double   g_pce[MAXBLK];
__device__ double   g_pms[MAXBLK];
__device__ unsigned g_count = 0;   // reset by the last block each call

#define NEG_INF (-__int_as_float(0x7f800000))

__global__ __launch_bounds__(256, 7) void row_kernel(
    const float* __restrict__ logits,
    const int*   __restrict__ l32,     // labels viewed as int32 words
    const float* __restrict__ features,
    const float* __restrict__ protos,
    float* __restrict__ out,
    int B, int C, int D)
{
    const int lane = threadIdx.x & 31;
    const int wid  = threadIdx.x >> 5;
    const int row  = blockIdx.x * 8 + wid;
    const bool active = (row < B);

    float ce_f = 0.0f, ms_f = 0.0f;

    if (active) {
        // ---- per-warp label dtype detection (first 64 int32 words = 256B) ----
        // int64 labels < C  =>  all odd (high) words are 0.
        // int32 labels uniform [0,C)  =>  P(32 odd words all zero) ~ C^-32 ~ 0.
        int probe = l32[2 * lane + 1];
        bool lbl64 = (__ballot_sync(0xFFFFFFFFu, probe != 0) == 0u);
        const int label = lbl64 ? l32[2 * row] : l32[row];

        const float* lr = logits + (size_t)row * C;
        const float lbl_logit = __ldg(lr + label);   // warp-uniform broadcast

        const float4* lrow = (const float4*)lr;
        const int C4 = C >> 2;
        const int Ctail = C & 3;

        // ---- single-pass sum of exp (no max subtraction) ----
        float s = 0.0f;
        #pragma unroll 4
        for (int idx = lane; idx < C4; idx += 32) {
            float4 v = lrow[idx];
            s += __expf(v.x) + __expf(v.y) + __expf(v.z) + __expf(v.w);
        }
        if (lane < Ctail) s += __expf(lr[C4 * 4 + lane]);

        // ---- per-row proto MSE (independent memory stream) ----
        const float4* frow = (const float4*)(features + (size_t)row   * D);
        const float4* prow = (const float4*)(protos   + (size_t)label * D);
        const int D4 = D >> 2;
        float sq = 0.0f;
        #pragma unroll 2
        for (int idx = lane; idx < D4; idx += 32) {
            float4 f = frow[idx];
            float4 p = prow[idx];
            float dx = f.x - p.x, dy = f.y - p.y, dz = f.z - p.z, dw = f.w - p.w;
            sq = fmaf(dx, dx, fmaf(dy, dy, fmaf(dz, dz, fmaf(dw, dw, sq))));
        }
        {
            const int Dtail = D & 3;
            if (lane < Dtail) {
                float d = features[(size_t)row * D + D4 * 4 + lane]
                        - protos[(size_t)label * D + D4 * 4 + lane];
                sq = fmaf(d, d, sq);
            }
        }

        // ---- warp sum reductions ----
        #pragma unroll
        for (int off = 16; off > 0; off >>= 1) {
            s  += __shfl_xor_sync(0xFFFFFFFFu, s,  off);
            sq += __shfl_xor_sync(0xFFFFFFFFu, sq, off);
        }

        float lse;
        if (__builtin_expect(isinf(s) || !(s > 0.0f), 0)) {
            // ---- rare fallback: classic two-pass max-subtracted logsumexp ----
            // (taken only if some |logit| >~ 88; reloads are cache-hot)
            float m = NEG_INF;
            for (int idx = lane; idx < C4; idx += 32) {
                float4 q = lrow[idx];
                m = fmaxf(m, fmaxf(fmaxf(q.x, q.y), fmaxf(q.z, q.w)));
            }
            if (lane < Ctail) m = fmaxf(m, lr[C4 * 4 + lane]);
            #pragma unroll
            for (int off = 16; off > 0; off >>= 1)
                m = fmaxf(m, __shfl_xor_sync(0xFFFFFFFFu, m, off));
            float s2 = 0.0f;
            for (int idx = lane; idx < C4; idx += 32) {
                float4 q = lrow[idx];
                s2 += __expf(q.x - m) + __expf(q.y - m)
                    + __expf(q.z - m) + __expf(q.w - m);
            }
            if (lane < Ctail) s2 += __expf(lr[C4 * 4 + lane] - m);
            #pragma unroll
            for (int off = 16; off > 0; off >>= 1)
                s2 += __shfl_xor_sync(0xFFFFFFFFu, s2, off);
            lse = m + __logf(s2);
        } else {
            lse = __logf(s);
        }

        ce_f = lse - lbl_logit;
        ms_f = sq / (float)D;
    }

    // ---- block reduction of the 8 warp results (doubles) ----
    __shared__ double sm_ce[8], sm_ms[8];
    __shared__ bool   s_is_last;
    if (lane == 0) { sm_ce[wid] = (double)ce_f; sm_ms[wid] = (double)ms_f; }
    __syncthreads();

    if (threadIdx.x == 0) {
        double bce = 0.0, bms = 0.0;
        #pragma unroll
        for (int j = 0; j < 8; j++) { bce += sm_ce[j]; bms += sm_ms[j]; }
        g_pce[blockIdx.x] = bce;
        g_pms[blockIdx.x] = bms;
        __threadfence();
        unsigned prev = atomicAdd(&g_count, 1u);
        s_is_last = (prev == gridDim.x - 1);
    }
    __syncthreads();

    // ---- last-arriving block: reduce L2-hot partials, emit outputs ----
    if (s_is_last) {
        const int tid = threadIdx.x;
        const int nb  = gridDim.x;
        double ce = 0.0, ms = 0.0;
        for (int i = tid; i < nb; i += 256) { ce += g_pce[i]; ms += g_pms[i]; }

        __shared__ double red[512];
        red[tid] = ce; red[256 + tid] = ms;
        __syncthreads();
        #pragma unroll
        for (int off = 128; off > 0; off >>= 1) {
            if (tid < off) {
                red[tid]       += red[tid + off];
                red[256 + tid] += red[256 + tid + off];
            }
            __syncthreads();
        }

        if (tid == 0) {
            float ce_loss = (float)(red[0] / (double)B);
            if (!isfinite(ce_loss)) ce_loss = 0.0f;
            float proto_loss = (float)(red[256] / (double)B);
            float total = ce_loss + proto_loss;
            if (!isfinite(total)) total = ce_loss;
            out[0] = total;
            out[1] = ce_loss;
            out[2] = proto_loss;
            g_count = 0;          // reset for next graph replay
        }
    }
}

extern "C" void kernel_launch(void* const* d_in, const int* in_sizes, int n_in,
                              void* d_out, int out_size) {
    const float* logits   = (const float*)d_in[0];
    const int*   labels   = (const int*)d_in[1];
    const float* features = (const float*)d_in[2];
    const float* protos   = (const float*)d_in[3];
    float* out = (float*)d_out;

    const int B = in_sizes[1];                 // 16384
    const int C = in_sizes[0] / B;             // 1000
    const int D = in_sizes[2] / B;             // 512

    const int blocks = (B + 7) / 8;            // one warp per row, 8 warps/block
    row_kernel<<<blocks, 256>>>(logits, labels, features, protos, out, B, C, D);
}